// round 15
// baseline (speedup 1.0000x reference)
#include <cuda_runtime.h>
#include <cuda_fp16.h>
#include <math.h>
#include <cstdint>

// Problem constants
#define BN_POS 2048      // B*N
#define MPAD   2304
#define NTILES 17
#define MDIM   32768
#define DDIM   1024
#define KSEL   32
#define NHEAD  16
#define GK     2048      // q-proj split-K (fp16 2-term: A=[hi|lo], B=[hi|hi])
#define BK     32
#define NKIT   (GK / BK) // 64
#define KOUT   1024      // out-GEMM split-K (P=[hi|lo], VWT=[hi|hi])
#define STAGES 5
#define SSTRIDE 40

// Scratch (device globals; no allocation allowed)
__device__ float g_c[MDIM];
__device__ int   g_sel[2][KSEL];
__device__ float g_kproj[2][KSEL][DDIM];
__device__ float g_vproj[2][KSEL][DDIM];
__device__ int   g_sign[BN_POS];
__device__ float g_wpart[32][DDIM];
__device__ int   g_permdst[BN_POS];
__device__ int   g_rowmap[MPAD];
__device__ int   g_tilesel[32];
__device__ __half g_As[(size_t)BN_POS * GK];     // X split [hi|lo]
__device__ __half g_Ws0[(size_t)DDIM * GK];      // Wq split [hi|hi]
__device__ float g_q[(size_t)BN_POS * DDIM];
__device__ float g_p[(size_t)BN_POS * 512];      // probs [pos][h*32+slot]
__device__ __half g_Ps[(size_t)MPAD * KOUT];     // P split [hi|lo], permuted
__device__ __half g_VWTs[2][1024][KOUT];         // VWT split [hi|hi]

// ---------------------------------------------------------------------------
// q-proj GEMM: C[m][n] = sum_k A[m][k]*B[n][k]. 128x128 CTA, fp16 HMMA.
// ---------------------------------------------------------------------------
#define GEMM_SMEM (STAGES * 128 * SSTRIDE * 2 * 2)

__global__ void __launch_bounds__(256) gemm_mma_kernel(
    const __half* __restrict__ A,
    const __half* __restrict__ Bm,
    float* __restrict__ C) {
    extern __shared__ __align__(16) __half sm[];
    __half* AsP = sm;
    __half* BsP = sm + STAGES * 128 * SSTRIDE;

    const int tid = threadIdx.x;
    const int wid = tid >> 5, lane = tid & 31;
    const int wm = wid >> 2, wn = wid & 3;
    const int tn0 = blockIdx.x * 128;
    const int tm0 = blockIdx.y * 128;

    const __half* Ag = A + (size_t)tm0 * GK;
    const __half* Bg = Bm + (size_t)tn0 * GK;

    const uint32_t smA = (uint32_t)__cvta_generic_to_shared(AsP);
    const uint32_t smB = (uint32_t)__cvta_generic_to_shared(BsP);

    float acc[4][4][4];
#pragma unroll
    for (int i = 0; i < 4; i++)
#pragma unroll
        for (int j = 0; j < 4; j++)
#pragma unroll
            for (int r = 0; r < 4; r++) acc[i][j][r] = 0.f;

    auto load_stage = [&](int it, int buf) {
        const int k0 = it * BK;
#pragma unroll
        for (int t = 0; t < 4; t++) {
            int ee = tid + t * 256;
            int row = (ee & 511) >> 2;
            int seg = ee & 3;
            const __half* gp;
            uint32_t sp;
            if (ee < 512) {
                gp = Ag + (size_t)row * GK + k0 + seg * 8;
                sp = smA + (uint32_t)(((buf * 128 + row) * SSTRIDE + seg * 8) * 2);
            } else {
                gp = Bg + (size_t)row * GK + k0 + seg * 8;
                sp = smB + (uint32_t)(((buf * 128 + row) * SSTRIDE + seg * 8) * 2);
            }
            asm volatile("cp.async.cg.shared.global [%0], [%1], 16;"
                         :: "r"(sp), "l"(gp));
        }
        asm volatile("cp.async.commit_group;" ::: "memory");
    };

    load_stage(0, 0); load_stage(1, 1); load_stage(2, 2); load_stage(3, 3);

    for (int it = 0; it < NKIT; it++) {
        const int buf = it % STAGES;
        asm volatile("cp.async.wait_group 3;" ::: "memory");
        __syncthreads();
        if (it + 4 < NKIT) {
            load_stage(it + 4, (it + 4) % STAGES);
        } else {
            asm volatile("cp.async.commit_group;" ::: "memory");
        }

#pragma unroll
        for (int ks = 0; ks < 2; ks++) {
            const int kb = ks * 16;
            uint32_t a[4][4], b[4][2];
            const int mat = lane >> 3, r8 = lane & 7;
#pragma unroll
            for (int mt = 0; mt < 4; mt++) {
                int row = wm * 64 + mt * 16 + (mat & 1) * 8 + r8;
                int col = kb + (mat >> 1) * 8;
                uint32_t ad = smA + (uint32_t)(((buf * 128 + row) * SSTRIDE + col) * 2);
                asm volatile(
                    "ldmatrix.sync.aligned.m8n8.x4.shared.b16 {%0,%1,%2,%3}, [%4];"
                    : "=r"(a[mt][0]), "=r"(a[mt][1]), "=r"(a[mt][2]), "=r"(a[mt][3])
                    : "r"(ad));
            }
#pragma unroll
            for (int p = 0; p < 2; p++) {
                int nrow = wn * 32 + p * 16 + (mat >> 1) * 8 + r8;
                int col = kb + (mat & 1) * 8;
                uint32_t bd = smB + (uint32_t)(((buf * 128 + nrow) * SSTRIDE + col) * 2);
                uint32_t q0, q1, q2, q3;
                asm volatile(
                    "ldmatrix.sync.aligned.m8n8.x4.shared.b16 {%0,%1,%2,%3}, [%4];"
                    : "=r"(q0), "=r"(q1), "=r"(q2), "=r"(q3)
                    : "r"(bd));
                b[2 * p][0] = q0; b[2 * p][1] = q1;
                b[2 * p + 1][0] = q2; b[2 * p + 1][1] = q3;
            }
#pragma unroll
            for (int mt = 0; mt < 4; mt++)
#pragma unroll
                for (int nt = 0; nt < 4; nt++) {
                    asm volatile(
                        "mma.sync.aligned.m16n8k16.row.col.f32.f16.f16.f32 "
                        "{%0,%1,%2,%3}, {%4,%5,%6,%7}, {%8,%9}, {%0,%1,%2,%3};"
                        : "+f"(acc[mt][nt][0]), "+f"(acc[mt][nt][1]),
                          "+f"(acc[mt][nt][2]), "+f"(acc[mt][nt][3])
                        : "r"(a[mt][0]), "r"(a[mt][1]), "r"(a[mt][2]), "r"(a[mt][3]),
                          "r"(b[nt][0]), "r"(b[nt][1]));
                }
        }
    }

    const int rl = lane >> 2, cl = (lane & 3) * 2;
#pragma unroll
    for (int mt = 0; mt < 4; mt++) {
        int row = tm0 + wm * 64 + mt * 16 + rl;
#pragma unroll
        for (int nt = 0; nt < 4; nt++) {
            int col = tn0 + wn * 32 + nt * 8 + cl;
            *(float2*)(C + (size_t)row * 1024 + col) =
                make_float2(acc[mt][nt][0], acc[mt][nt][1]);
            *(float2*)(C + (size_t)(row + 8) * 1024 + col) =
                make_float2(acc[mt][nt][2], acc[mt][nt][3]);
        }
    }
}

// ---------------------------------------------------------------------------
// Output GEMM: out[pos][p] = P[row] . VWT[sel][p] + bo[p].
// NT=128, KTOT=KOUT=1024, rowmap scatter, per-tile B select. fp16 HMMA.
// ---------------------------------------------------------------------------
#define SM_OUT (STAGES * (128 + 128) * SSTRIDE * 2)

__global__ void __launch_bounds__(256) gemm_out_kernel(
    const __half* __restrict__ A,
    const __half* __restrict__ B0,
    const __half* __restrict__ B1,
    float* __restrict__ C,
    const float* __restrict__ bias) {
    constexpr int KTOT = KOUT;
    constexpr int NKITL = KTOT / BK;   // 32
    extern __shared__ __align__(16) char rawsm[];
    __half* AsP = (__half*)rawsm;
    __half* BsP = AsP + STAGES * 128 * SSTRIDE;

    const int tid = threadIdx.x;
    const int wid = tid >> 5, lane = tid & 31;
    const int wm = wid >> 2, wn = wid & 3;
    const int tn0 = blockIdx.x * 128;
    const int mrow0 = blockIdx.y * 128;
    const int bsel = g_tilesel[blockIdx.y];
    const __half* Bm = bsel ? B1 : B0;

    const __half* Ag = A + (size_t)mrow0 * KTOT;
    const __half* Bg = Bm + (size_t)tn0 * KTOT;

    const uint32_t smA = (uint32_t)__cvta_generic_to_shared(AsP);
    const uint32_t smB = (uint32_t)__cvta_generic_to_shared(BsP);

    float acc[4][4][4];
#pragma unroll
    for (int i = 0; i < 4; i++)
#pragma unroll
        for (int j = 0; j < 4; j++)
#pragma unroll
            for (int r = 0; r < 4; r++) acc[i][j][r] = 0.f;

    auto load_stage = [&](int it, int buf) {
        const int k0 = it * BK;
#pragma unroll
        for (int t = 0; t < 4; t++) {
            int ee = tid + t * 256;
            int row = (ee & 511) >> 2;
            int seg = ee & 3;
            const __half* gp;
            uint32_t sp;
            if (ee < 512) {
                gp = Ag + (size_t)row * KTOT + k0 + seg * 8;
                sp = smA + (uint32_t)(((buf * 128 + row) * SSTRIDE + seg * 8) * 2);
            } else {
                gp = Bg + (size_t)row * KTOT + k0 + seg * 8;
                sp = smB + (uint32_t)(((buf * 128 + row) * SSTRIDE + seg * 8) * 2);
            }
            asm volatile("cp.async.cg.shared.global [%0], [%1], 16;"
                         :: "r"(sp), "l"(gp));
        }
        asm volatile("cp.async.commit_group;" ::: "memory");
    };

    load_stage(0, 0); load_stage(1, 1); load_stage(2, 2); load_stage(3, 3);

    for (int it = 0; it < NKITL; it++) {
        const int buf = it % STAGES;
        asm volatile("cp.async.wait_group 3;" ::: "memory");
        __syncthreads();
        if (it + 4 < NKITL) {
            load_stage(it + 4, (it + 4) % STAGES);
        } else {
            asm volatile("cp.async.commit_group;" ::: "memory");
        }

#pragma unroll
        for (int ks = 0; ks < 2; ks++) {
            const int kb = ks * 16;
            uint32_t a[4][4], b[4][2];
            const int mat = lane >> 3, r8 = lane & 7;
#pragma unroll
            for (int mt = 0; mt < 4; mt++) {
                int row = wm * 64 + mt * 16 + (mat & 1) * 8 + r8;
                int col = kb + (mat >> 1) * 8;
                uint32_t ad = smA + (uint32_t)(((buf * 128 + row) * SSTRIDE + col) * 2);
                asm volatile(
                    "ldmatrix.sync.aligned.m8n8.x4.shared.b16 {%0,%1,%2,%3}, [%4];"
                    : "=r"(a[mt][0]), "=r"(a[mt][1]), "=r"(a[mt][2]), "=r"(a[mt][3])
                    : "r"(ad));
            }
#pragma unroll
            for (int p = 0; p < 2; p++) {
                int nrow = wn * 32 + p * 16 + (mat >> 1) * 8 + r8;
                int col = kb + (mat & 1) * 8;
                uint32_t bd = smB + (uint32_t)(((buf * 128 + nrow) * SSTRIDE + col) * 2);
                uint32_t q0, q1, q2, q3;
                asm volatile(
                    "ldmatrix.sync.aligned.m8n8.x4.shared.b16 {%0,%1,%2,%3}, [%4];"
                    : "=r"(q0), "=r"(q1), "=r"(q2), "=r"(q3)
                    : "r"(bd));
                b[2 * p][0] = q0; b[2 * p][1] = q1;
                b[2 * p + 1][0] = q2; b[2 * p + 1][1] = q3;
            }
#pragma unroll
            for (int mt = 0; mt < 4; mt++)
#pragma unroll
                for (int nt = 0; nt < 4; nt++) {
                    asm volatile(
                        "mma.sync.aligned.m16n8k16.row.col.f32.f16.f16.f32 "
                        "{%0,%1,%2,%3}, {%4,%5,%6,%7}, {%8,%9}, {%0,%1,%2,%3};"
                        : "+f"(acc[mt][nt][0]), "+f"(acc[mt][nt][1]),
                          "+f"(acc[mt][nt][2]), "+f"(acc[mt][nt][3])
                        : "r"(a[mt][0]), "r"(a[mt][1]), "r"(a[mt][2]), "r"(a[mt][3]),
                          "r"(b[nt][0]), "r"(b[nt][1]));
                }
        }
    }

    const int rl = lane >> 2, cl = (lane & 3) * 2;
#pragma unroll
    for (int mt = 0; mt < 4; mt++) {
        int grow = mrow0 + wm * 64 + mt * 16 + rl;
        int pos0 = g_rowmap[grow], pos1 = g_rowmap[grow + 8];
#pragma unroll
        for (int nt = 0; nt < 4; nt++) {
            int col = tn0 + wn * 32 + nt * 8 + cl;
            float b0 = bias[col], b1 = bias[col + 1];
            if (pos0 >= 0)
                *(float2*)(C + (size_t)pos0 * 1024 + col) =
                    make_float2(acc[mt][nt][0] + b0, acc[mt][nt][1] + b1);
            if (pos1 >= 0)
                *(float2*)(C + (size_t)pos1 * 1024 + col) =
                    make_float2(acc[mt][nt][2] + b0, acc[mt][nt][3] + b1);
        }
    }
}

// ---------------------------------------------------------------------------
// fp16 splits. act: [hi|lo].  weight: [hi|hi].
// ---------------------------------------------------------------------------
__device__ __forceinline__ void split_row_act(const float* __restrict__ in,
                                              __half* __restrict__ out, size_t idx) {
    int row = (int)(idx >> 10);
    int k = (int)(idx & 1023);
    float4 v = *(const float4*)(in + idx);
    __half h0 = __float2half_rn(v.x), h1 = __float2half_rn(v.y);
    __half h2 = __float2half_rn(v.z), h3 = __float2half_rn(v.w);
    __half l0 = __float2half_rn(v.x - __half2float(h0));
    __half l1 = __float2half_rn(v.y - __half2float(h1));
    __half l2 = __float2half_rn(v.z - __half2float(h2));
    __half l3 = __float2half_rn(v.w - __half2float(h3));
    __half2* o0 = (__half2*)(out + (size_t)row * GK + k);
    __half2* o1 = (__half2*)(out + (size_t)row * GK + 1024 + k);
    o0[0] = __halves2half2(h0, h1); o0[1] = __halves2half2(h2, h3);
    o1[0] = __halves2half2(l0, l1); o1[1] = __halves2half2(l2, l3);
}

__device__ __forceinline__ void split_row_w(const float* __restrict__ in,
                                            __half* __restrict__ out, size_t idx) {
    int row = (int)(idx >> 10);
    int k = (int)(idx & 1023);
    float4 v = *(const float4*)(in + idx);
    __half2 a = __halves2half2(__float2half_rn(v.x), __float2half_rn(v.y));
    __half2 b = __halves2half2(__float2half_rn(v.z), __float2half_rn(v.w));
    __half2* o0 = (__half2*)(out + (size_t)row * GK + k);
    __half2* o1 = (__half2*)(out + (size_t)row * GK + 1024 + k);
    o0[0] = a; o0[1] = b;
    o1[0] = a; o1[1] = b;
}

// blocks [0,1024)=Wq->Ws0, [1024,3072)=X->As
__global__ void __launch_bounds__(256) fused_split_kernel(
    const float* __restrict__ Wq, const float* __restrict__ X) {
    int b = blockIdx.x;
    if (b < 1024)
        split_row_w(Wq, g_Ws0, ((size_t)b * 256 + threadIdx.x) * 4);
    else
        split_row_act(X, g_As, ((size_t)(b - 1024) * 256 + threadIdx.x) * 4);
}

// ---------------------------------------------------------------------------
// c[m] = sum(keys[m]) / (sqrt(D) * ||keys[m]||)
// ---------------------------------------------------------------------------
__global__ void __launch_bounds__(256) compute_c_kernel(const float* __restrict__ keys) {
    int warp = threadIdx.x >> 5;
    int lane = threadIdx.x & 31;
    int row  = blockIdx.x * 8 + warp;
    const float4* kp = reinterpret_cast<const float4*>(keys + (size_t)row * DDIM);
    float s = 0.f, ss = 0.f;
#pragma unroll
    for (int i = 0; i < 8; i++) {
        float4 v = kp[lane + i * 32];
        s  += (v.x + v.y) + (v.z + v.w);
        ss += v.x * v.x + v.y * v.y + v.z * v.z + v.w * v.w;
    }
#pragma unroll
    for (int o = 16; o > 0; o >>= 1) {
        s  += __shfl_xor_sync(0xffffffffu, s, o);
        ss += __shfl_xor_sync(0xffffffffu, ss, o);
    }
    if (lane == 0) g_c[row] = s / (32.0f * sqrtf(ss));
}

// ---------------------------------------------------------------------------
// Fast select
// ---------------------------------------------------------------------------
__global__ void __launch_bounds__(1024) select_kernel() {
    __shared__ float wlv[32][33];
    __shared__ int   wli[32][33];
    const int tid = threadIdx.x;
    const int lane = tid & 31, w = tid >> 5;
    const int phase = blockIdx.x;

    float v[32];
#pragma unroll
    for (int j = 0; j < 32; j++) v[j] = g_c[w * 1024 + j * 32 + lane];

    float bv = v[0]; int bj = 0;
#pragma unroll
    for (int j = 1; j < 32; j++) {
        bool bet = phase ? (v[j] < bv) : (v[j] > bv);
        if (bet) { bv = v[j]; bj = j; }
    }

    for (int r = 0; r < 32; r++) {
        float cv = bv;
        int ci = w * 1024 + bj * 32 + lane;
#pragma unroll
        for (int o = 16; o > 0; o >>= 1) {
            float ov = __shfl_xor_sync(0xffffffffu, cv, o);
            int   oi = __shfl_xor_sync(0xffffffffu, ci, o);
            bool bet = phase ? ((ov < cv) || (ov == cv && oi < ci))
                             : ((ov > cv) || (ov == cv && oi < ci));
            if (bet) { cv = ov; ci = oi; }
        }
        if (lane == 0) { wlv[w][r] = cv; wli[w][r] = ci; }
        int wlane = ci & 31;
        if (lane == wlane && r < 31) {
            int wj = (ci >> 5) & 31;
            v[wj] = phase ? INFINITY : -INFINITY;
            bv = v[0]; bj = 0;
#pragma unroll
            for (int j = 1; j < 32; j++) {
                bool bet = phase ? (v[j] < bv) : (v[j] > bv);
                if (bet) { bv = v[j]; bj = j; }
            }
        }
    }
    __syncthreads();

    if (w == 0) {
        int ptr = 0;
        for (int r = 0; r < 32; r++) {
            float hv = wlv[lane][ptr];
            int   hidx = wli[lane][ptr];
            float cv = hv; int ci = hidx;
#pragma unroll
            for (int o = 16; o > 0; o >>= 1) {
                float ov = __shfl_xor_sync(0xffffffffu, cv, o);
                int   oi = __shfl_xor_sync(0xffffffffu, ci, o);
                bool bet = phase ? ((ov < cv) || (ov == cv && oi < ci))
                                 : ((ov > cv) || (ov == cv && oi < ci));
                if (bet) { cv = ov; ci = oi; }
            }
            if (hv == cv && hidx == ci) ptr++;
            if (lane == 0) g_sel[phase][r] = ci;
        }
    }
}

// ---------------------------------------------------------------------------
// wbar + sign(qm)
// ---------------------------------------------------------------------------
__global__ void __launch_bounds__(128) wbar_kernel(const float* __restrict__ Wq) {
    int col = blockIdx.x * 128 + threadIdx.x;
    int o0 = blockIdx.y * 32;
    float s = 0.f;
#pragma unroll 8
    for (int o = 0; o < 32; o++)
        s += Wq[(size_t)(o0 + o) * DDIM + col];
    g_wpart[blockIdx.y][col] = s;
}

__global__ void __launch_bounds__(256) qm_sign_kernel(const float* __restrict__ X) {
    __shared__ float wb[DDIM];
    const int tid = threadIdx.x;
    for (int c = tid; c < DDIM; c += 256) {
        float s = 0.f;
#pragma unroll
        for (int by = 0; by < 32; by++) s += g_wpart[by][c];
        wb[c] = s;
    }
    __syncthreads();
    const int lane = tid & 31, w = tid >> 5;
    int row = blockIdx.x * 8 + w;
    const float4* xp = reinterpret_cast<const float4*>(X + (size_t)row * DDIM);
    const float4* wp = reinterpret_cast<const float4*>(wb);
    float s = 0.f;
#pragma unroll
    for (int i = 0; i < 8; i++) {
        float4 a = xp[lane + i * 32];
        float4 b = wp[lane + i * 32];
        s += a.x * b.x + a.y * b.y + a.z * b.z + a.w * b.w;
    }
#pragma unroll
    for (int o = 16; o > 0; o >>= 1) s += __shfl_xor_sync(0xffffffffu, s, o);
    if (lane == 0) g_sign[row] = (s >= 0.f) ? 0 : 1;
}

// ---------------------------------------------------------------------------
// Stable partition
// ---------------------------------------------------------------------------
__global__ void __launch_bounds__(1024) perm_kernel() {
    __shared__ int sa[2048];
    __shared__ int sb[2048];
    const int tid = threadIdx.x;
    int z0 = (g_sign[tid] == 0);
    int z1 = (g_sign[tid + 1024] == 0);
    sa[tid] = z0; sa[tid + 1024] = z1;
    __syncthreads();
    int* src = sa; int* dst = sb;
    for (int off = 1; off < 2048; off <<= 1) {
        int i0 = tid, i1 = tid + 1024;
        dst[i0] = src[i0] + (i0 >= off ? src[i0 - off] : 0);
        dst[i1] = src[i1] + (i1 >= off ? src[i1 - off] : 0);
        __syncthreads();
        int* t = src; src = dst; dst = t;
    }
    int* scan = src;
    int M0 = scan[2047];
    int t0 = (M0 + 127) >> 7;
    int G1 = t0 << 7;

    g_rowmap[tid] = -1;
    g_rowmap[tid + 1024] = -1;
    if (tid < MPAD - 2048) g_rowmap[2048 + tid] = -1;
    __syncthreads();

    int d0 = z0 ? (scan[tid] - 1) : (G1 + tid - scan[tid]);
    int i1 = tid + 1024;
    int d1 = z1 ? (scan[i1] - 1) : (G1 + i1 - scan[i1]);
    g_permdst[tid] = d0;
    g_permdst[i1] = d1;
    g_rowmap[d0] = tid;
    g_rowmap[d1] = i1;
    if (tid < NTILES) g_tilesel[tid] = (tid < t0) ? 0 : 1;
}

// ---------------------------------------------------------------------------
// K/V projections
// ---------------------------------------------------------------------------
__global__ void __launch_bounds__(256) kvproj_kernel(const float* __restrict__ keys,
                                                     const float* __restrict__ vals,
                                                     const float* __restrict__ Wk,
                                                     const float* __restrict__ Wv) {
    __shared__ float As[32][64];
    __shared__ float Bs[64][68];
    __shared__ int sidx[32];
    const int tid = threadIdx.x;
    const int col0 = blockIdx.x * 64;
    const int sel = blockIdx.y;
    const int mat = blockIdx.z;
    const float* src = mat ? vals : keys;
    const float* W   = mat ? Wv : Wk;
    float* dst = mat ? &g_vproj[sel][0][0] : &g_kproj[sel][0][0];
    if (tid < 32) sidx[tid] = g_sel[sel][tid];
    __syncthreads();
    const int tx = tid & 7, ty = tid >> 3;
    float acc[8] = {};
    for (int kk = 0; kk < DDIM; kk += 64) {
#pragma unroll
        for (int t = 0; t < 2; t++) {
            int e = tid + t * 256;
            int slot = e >> 4, f4 = e & 15;
            *reinterpret_cast<float4*>(&As[slot][f4 * 4]) =
                *reinterpret_cast<const float4*>(&src[(size_t)sidx[slot] * DDIM + kk + f4 * 4]);
        }
#pragma unroll
        for (int t = 0; t < 4; t++) {
            int e = tid + t * 256;
            int col = e >> 4, f4 = e & 15;
            float4 v = *reinterpret_cast<const float4*>(&W[(size_t)(col0 + col) * DDIM + kk + f4 * 4]);
            Bs[f4 * 4 + 0][col] = v.x; Bs[f4 * 4 + 1][col] = v.y;
            Bs[f4 * 4 + 2][col] = v.z; Bs[f4 * 4 + 3][col] = v.w;
        }
        __syncthreads();
#pragma unroll
        for (int k = 0; k < 64; k++) {
            float a = As[ty][k];
#pragma unroll
            for (int j = 0; j < 8; j++)
                acc[j] = fmaf(a, Bs[k][tx * 8 + j], acc[j]);
        }
        __syncthreads();
    }
#pragma unroll
    for (int j = 0; j < 8; j += 4)
        *reinterpret_cast<float4*>(&dst[(size_t)ty * DDIM + col0 + tx * 8 + j]) =
            make_float4(acc[j], acc[j + 1], acc[j + 2], acc[j + 3]);
}

// ---------------------------------------------------------------------------
// VWT[sel][p][h*32+slot] = sum_e Vproj[sel][slot][h*64+e] * Wo[p][h*64+e]
// fp16 [hi|hi] epilogue over K=1024.
// ---------------------------------------------------------------------------
__global__ void __launch_bounds__(256) vw_kernel(const float* __restrict__ Wo) {
    __shared__ float Vp[32][68];
    __shared__ float Wos[64][68];
    const int tid = threadIdx.x;
    const int pt = blockIdx.x, h = blockIdx.y, sel = blockIdx.z;
#pragma unroll
    for (int t = 0; t < 2; t++) {
        int e = tid + t * 256;
        int slot = e >> 4, f4 = e & 15;
        *(float4*)(&Vp[slot][f4 * 4]) =
            *(const float4*)(&g_vproj[sel][slot][h * 64 + f4 * 4]);
    }
#pragma unroll
    for (int t = 0; t < 4; t++) {
        int e = tid + t * 256;
        int pl = e >> 4, f4 = e & 15;
        *(float4*)(&Wos[pl][f4 * 4]) =
            *(const float4*)(&Wo[(size_t)(pt * 64 + pl) * DDIM + h * 64 + f4 * 4]);
    }
    __syncthreads();
    const int pl = tid >> 2, s0 = (tid & 3) * 8;
    float acc[8] = {};
#pragma unroll
    for (int k4 = 0; k4 < 16; k4++) {
        float4 w = *(const float4*)(&Wos[pl][k4 * 4]);
#pragma unroll
        for (int j = 0; j < 8; j++) {
            float4 vv = *(const float4*)(&Vp[s0 + j][k4 * 4]);
            acc[j] = fmaf(w.x, vv.x, acc[j]);
            acc[j] = fmaf(w.y, vv.y, acc[j]);
            acc[j] = fmaf(w.z, vv.z, acc[j]);
            acc[j] = fmaf(w.w, vv.w, acc[j]);
        }
    }
    const int p = pt * 64 + pl;
    __half* out = &g_VWTs[sel][p][0];
#pragma unroll
    for (int j = 0; j < 8; j++) {
        int hs = h * 32 + s0 + j;
        __half hi = __float2half_rn(acc[j]);
        out[hs] = hi; out[512 + hs] = hi;
    }
}

// ---------------------------------------------------------------------------
// scores+softmax: 32 pos x 16 heads -> g_p[pos][h*32+slot]
// ---------------------------------------------------------------------------
__global__ void __launch_bounds__(256) scores_kernel() {
    __shared__ float Ks[2][32][65];
    __shared__ float qs[32][65];
    __shared__ int ssel[32];
    const int tid = threadIdx.x;
    const int p0 = blockIdx.x * 32;
    const int h = blockIdx.y;

#pragma unroll
    for (int t = 0; t < 4; t++) {
        int e = tid + t * 256;
        int sel = e >> 9, slot = (e >> 4) & 31, f4 = e & 15;
        float4 v = *(const float4*)(&g_kproj[sel][slot][h * 64 + f4 * 4]);
        Ks[sel][slot][f4 * 4 + 0] = v.x; Ks[sel][slot][f4 * 4 + 1] = v.y;
        Ks[sel][slot][f4 * 4 + 2] = v.z; Ks[sel][slot][f4 * 4 + 3] = v.w;
    }
#pragma unroll
    for (int t = 0; t < 2; t++) {
        int e = tid + t * 256;
        int pos = e >> 4, f4 = e & 15;
        float4 v = *(const float4*)(&g_q[(size_t)(p0 + pos) * DDIM + h * 64 + f4 * 4]);
        qs[pos][f4 * 4 + 0] = v.x; qs[pos][f4 * 4 + 1] = v.y;
        qs[pos][f4 * 4 + 2] = v.z; qs[pos][f4 * 4 + 3] = v.w;
    }
    if (tid < 32) ssel[tid] = g_sign[p0 + tid];
    __syncthreads();

    const int w = tid >> 5, lane = tid & 31;
#pragma unroll
    for (int pi = 0; pi < 4; pi++) {
        int pos = w * 4 + pi;
        int sel = ssel[pos];
        const float* kr = &Ks[sel][lane][0];
        const float* qr = &qs[pos][0];
        float s = 0.f;
#pragma unroll
        for (int k = 0; k < 64; k++) s = fmaf(qr[k], kr[k], s);
        s *= 0.125f;
        float mx = s;
#pragma unroll
        for (int o = 16; o > 0; o >>= 1)
            mx = fmaxf(mx, __shfl_xor_sync(0xffffffffu, mx, o));
        float e = expf(s - mx);
        float sm = e;
#pragma unroll
        for (int o = 16; o > 0; o >>= 1)
            sm += __shfl_xor_sync(0xffffffffu, sm, o);
        g_p[(size_t)(p0 + pos) * 512 + h * 32 + lane] = e / sm;
    }
}

// ---------------------------------------------------------------------------
// pack P: g_Ps[permdst[pos]] = fp16 split(g_p[pos]) [hi|lo] over K=1024
// ---------------------------------------------------------------------------
__global__ void __launch_bounds__(128) packp_kernel() {
    const int pos = blockIdx.x;
    const int dst = g_permdst[pos];
    const int k = threadIdx.x * 4;
    float4 v = *(const float4*)(g_p + (size_t)pos * 512 + k);
    __half h0 = __float2half_rn(v.x), h1 = __float2half_rn(v.y);
    __half h2 = __float2half_rn(v.z), h3 = __float2half_rn(v.w);
    __half l0 = __float2half_rn(v.x - __half2float(h0));
    __half l1 = __float2half_rn(v.y - __half2float(h1));
    __half l2 = __float2half_rn(v.z - __half2float(h2));
    __half l3 = __float2half_rn(v.w - __half2float(h3));
    size_t base = (size_t)dst * KOUT + k;
    *(__half2*)(g_Ps + base)       = __halves2half2(h0, h1);
    *(__half2*)(g_Ps + base + 2)   = __halves2half2(h2, h3);
    *(__half2*)(g_Ps + base + 512) = __halves2half2(l0, l1);
    *(__half2*)(g_Ps + base + 514) = __halves2half2(l2, l3);
}

// ---------------------------------------------------------------------------
// avg_attn + sel_idx
// ---------------------------------------------------------------------------
__global__ void __launch_bounds__(256) avgsel_kernel(float* __restrict__ out_attn,
                                                     float* __restrict__ out_selidx) {
    const int tid = threadIdx.x;
    const int pos = blockIdx.x * 8 + (tid >> 5);
    const int slot = tid & 31;
    float s = 0.f;
#pragma unroll
    for (int hh = 0; hh < NHEAD; hh++)
        s += g_p[(size_t)pos * 512 + hh * 32 + slot];
    if (out_attn)
        out_attn[(size_t)pos * KSEL + slot] = s * (1.f / NHEAD);
    if (out_selidx)
        out_selidx[(size_t)pos * KSEL + slot] = (float)g_sel[g_sign[pos]][slot];
}

// ---------------------------------------------------------------------------
// LayerNorm in-place
// ---------------------------------------------------------------------------
__global__ void __launch_bounds__(256) ln_kernel(float* __restrict__ io,
                                                 const float* __restrict__ gamma,
                                                 const float* __restrict__ beta) {
    int row = blockIdx.x;
    float4* p = reinterpret_cast<float4*>(io + (size_t)row * DDIM);
    float4 v = p[threadIdx.x];
    float s  = (v.x + v.y) + (v.z + v.w);
    float ss = v.x * v.x + v.y * v.y + v.z * v.z + v.w * v.w;
    __shared__ float r1[8], r2[8];
    __shared__ float fmu, frs;
    int lane = threadIdx.x & 31, w = threadIdx.x >> 5;
#pragma unroll
    for (int o = 16; o > 0; o >>= 1) {
        s  += __shfl_xor_sync(0xffffffffu, s, o);
        ss += __shfl_xor_sync(0xffffffffu, ss, o);
    }
    if (lane == 0) { r1[w] = s; r2[w] = ss; }
    __syncthreads();
    if (threadIdx.x == 0) {
        float ts = 0.f, tss = 0.f;
#pragma unroll
        for (int i = 0; i < 8; i++) { ts += r1[i]; tss += r2[i]; }
        float mu  = ts * (1.f / 1024.f);
        float var = tss * (1.f / 1024.f) - mu * mu;
        fmu = mu;
        frs = rsqrtf(var + 1e-5f);
    }
    __syncthreads();
    float mu = fmu, rstd = frs;
    const float4 g = reinterpret_cast<const float4*>(gamma)[threadIdx.x];
    const float4 b = reinterpret_cast<const float4*>(beta)[threadIdx.x];
    v.x = (v.x - mu) * rstd * g.x + b.x;
    v.y = (v.y - mu) * rstd * g.y + b.y;
    v.z = (v.z - mu) * rstd * g.z + b.z;
    v.w = (v.w - mu) * rstd * g.w + b.w;
    p[threadIdx.x] = v;
}

// ---------------------------------------------------------------------------
extern "C" void kernel_launch(void* const* d_in, const int* in_sizes, int n_in,
                              void* d_out, int out_size) {
    const float* X     = (const float*)d_in[0];
    const float* keys  = (const float*)d_in[1];
    const float* vals  = (const float*)d_in[2];
    const float* Wq    = (const float*)d_in[3];
    const float* Wk    = (const float*)d_in[4];
    const float* Wv    = (const float*)d_in[5];
    const float* Wo    = (const float*)d_in[6];
    const float* bo    = (const float*)d_in[7];
    const float* gamma = (const float*)d_in[8];
    const float* beta  = (const float*)d_in[9];

    float* out = (float*)d_out;
    float* out_attn = nullptr;
    float* out_sel  = nullptr;
    const long long base = (long long)BN_POS * DDIM;
    if ((long long)out_size >= base + (long long)BN_POS * KSEL)
        out_attn = out + base;
    if ((long long)out_size >= base + 2LL * BN_POS * KSEL)
        out_sel = out + base + (long long)BN_POS * KSEL;

    void *pAs = nullptr, *pWs0 = nullptr, *pQ = nullptr, *pPs = nullptr, *pVW = nullptr;
    cudaGetSymbolAddress(&pAs, g_As);
    cudaGetSymbolAddress(&pWs0, g_Ws0);
    cudaGetSymbolAddress(&pQ, g_q);
    cudaGetSymbolAddress(&pPs, g_Ps);
    cudaGetSymbolAddress(&pVW, g_VWTs);
    __half* VW0 = (__half*)pVW;
    __half* VW1 = VW0 + (size_t)1024 * KOUT;

    cudaFuncSetAttribute(gemm_mma_kernel,
                         cudaFuncAttributeMaxDynamicSharedMemorySize, GEMM_SMEM);
    cudaFuncSetAttribute(gemm_out_kernel,
                         cudaFuncAttributeMaxDynamicSharedMemorySize, SM_OUT);

    static cudaStream_t s2 = nullptr, s3 = nullptr;
    static cudaEvent_t evFork = nullptr, ev2 = nullptr, ev2b = nullptr, ev3 = nullptr;
    if (!s2) {
        cudaStreamCreateWithFlags(&s2, cudaStreamNonBlocking);
        cudaStreamCreateWithFlags(&s3, cudaStreamNonBlocking);
        cudaEventCreateWithFlags(&evFork, cudaEventDisableTiming);
        cudaEventCreateWithFlags(&ev2, cudaEventDisableTiming);
        cudaEventCreateWithFlags(&ev2b, cudaEventDisableTiming);
        cudaEventCreateWithFlags(&ev3, cudaEventDisableTiming);
    }

    cudaEventRecord(evFork, 0);
    cudaStreamWaitEvent(s2, evFork, 0);
    cudaStreamWaitEvent(s3, evFork, 0);

    // ---- s2: selection chain; ev2 gates scores, ev2b gates gemm_out ----
    compute_c_kernel<<<MDIM / 8, 256, 0, s2>>>(keys);
    select_kernel<<<2, 1024, 0, s2>>>();
    kvproj_kernel<<<dim3(16, 2, 2), 256, 0, s2>>>(keys, vals, Wk, Wv);
    cudaEventRecord(ev2, s2);                 // scores needs only kproj
    vw_kernel<<<dim3(16, 16, 2), 256, 0, s2>>>(Wo);
    cudaEventRecord(ev2b, s2);                // gemm_out needs VWT

    // ---- s3: sign + permutation ----
    wbar_kernel<<<dim3(8, 32), 128, 0, s3>>>(Wq);
    qm_sign_kernel<<<BN_POS / 8, 256, 0, s3>>>(X);
    perm_kernel<<<1, 1024, 0, s3>>>();
    cudaEventRecord(ev3, s3);

    // ---- main: split + q-proj GEMM (independent of selection) ----
    fused_split_kernel<<<3072, 256>>>(Wq, X);
    gemm_mma_kernel<<<dim3(8, 16), 256, GEMM_SMEM>>>(
        (const __half*)pAs, (const __half*)pWs0, (float*)pQ);

    cudaStreamWaitEvent(0, ev2, 0);
    cudaStreamWaitEvent(0, ev3, 0);

    // ---- attention + output ----
    scores_kernel<<<dim3(BN_POS / 32, NHEAD), 256>>>();
    packp_kernel<<<BN_POS, 128>>>();
    avgsel_kernel<<<BN_POS / 8, 256>>>(out_attn, out_sel);
    cudaStreamWaitEvent(0, ev2b, 0);
    gemm_out_kernel<<<dim3(8, NTILES), 256, SM_OUT>>>(
        (const __half*)pPs, VW0, VW1, out, bo);
    ln_kernel<<<BN_POS, 256>>>(out, gamma, beta);
}

// round 16
// speedup vs baseline: 1.4961x; 1.4961x over previous
#include <cuda_runtime.h>
#include <cuda_fp16.h>
#include <math.h>
#include <cstdint>

// Problem constants
#define BN_POS 2048      // B*N
#define MPAD   2304
#define NTILES 17
#define MDIM   32768
#define DDIM   1024
#define KSEL   32
#define NHEAD  16
#define GK     2048      // q-proj split-K (fp16 2-term: A=[hi|lo], B=[hi|hi])
#define BK     32
#define NKIT   (GK / BK) // 64
#define KOUT   1024      // out-GEMM split-K (P=[hi|lo], VWT=[hi|hi])
#define STAGES 5
#define SSTRIDE 40

// Scratch (device globals; no allocation allowed)
__device__ float g_c[MDIM];
__device__ int   g_sel[2][KSEL];
__device__ float g_kproj[2][KSEL][DDIM];
__device__ float g_vproj[2][KSEL][DDIM];
__device__ int   g_sign[BN_POS];
__device__ float g_wpart[32][DDIM];
__device__ int   g_permdst[BN_POS];
__device__ int   g_rowmap[MPAD];
__device__ int   g_tilesel[32];
__device__ __half g_As[(size_t)BN_POS * GK];     // X split [hi|lo]
__device__ __half g_Ws0[(size_t)DDIM * GK];      // Wq split [hi|hi]
__device__ float g_q[(size_t)BN_POS * DDIM];
__device__ float g_p[(size_t)BN_POS * 512];      // probs [pos][h*32+slot]
__device__ __half g_Ps[(size_t)MPAD * KOUT];     // P split [hi|lo], permuted
__device__ __half g_VWTs[2][1024][KOUT];         // VWT split [hi|hi]

// ---------------------------------------------------------------------------
// q-proj GEMM: C[m][n] = sum_k A[m][k]*B[n][k]. 128x128 CTA, fp16 HMMA.
// ---------------------------------------------------------------------------
#define GEMM_SMEM (STAGES * 128 * SSTRIDE * 2 * 2)

__global__ void __launch_bounds__(256) gemm_mma_kernel(
    const __half* __restrict__ A,
    const __half* __restrict__ Bm,
    float* __restrict__ C) {
    extern __shared__ __align__(16) __half sm[];
    __half* AsP = sm;
    __half* BsP = sm + STAGES * 128 * SSTRIDE;

    const int tid = threadIdx.x;
    const int wid = tid >> 5, lane = tid & 31;
    const int wm = wid >> 2, wn = wid & 3;
    const int tn0 = blockIdx.x * 128;
    const int tm0 = blockIdx.y * 128;

    const __half* Ag = A + (size_t)tm0 * GK;
    const __half* Bg = Bm + (size_t)tn0 * GK;

    const uint32_t smA = (uint32_t)__cvta_generic_to_shared(AsP);
    const uint32_t smB = (uint32_t)__cvta_generic_to_shared(BsP);

    float acc[4][4][4];
#pragma unroll
    for (int i = 0; i < 4; i++)
#pragma unroll
        for (int j = 0; j < 4; j++)
#pragma unroll
            for (int r = 0; r < 4; r++) acc[i][j][r] = 0.f;

    auto load_stage = [&](int it, int buf) {
        const int k0 = it * BK;
#pragma unroll
        for (int t = 0; t < 4; t++) {
            int ee = tid + t * 256;
            int row = (ee & 511) >> 2;
            int seg = ee & 3;
            const __half* gp;
            uint32_t sp;
            if (ee < 512) {
                gp = Ag + (size_t)row * GK + k0 + seg * 8;
                sp = smA + (uint32_t)(((buf * 128 + row) * SSTRIDE + seg * 8) * 2);
            } else {
                gp = Bg + (size_t)row * GK + k0 + seg * 8;
                sp = smB + (uint32_t)(((buf * 128 + row) * SSTRIDE + seg * 8) * 2);
            }
            asm volatile("cp.async.cg.shared.global [%0], [%1], 16;"
                         :: "r"(sp), "l"(gp));
        }
        asm volatile("cp.async.commit_group;" ::: "memory");
    };

    load_stage(0, 0); load_stage(1, 1); load_stage(2, 2); load_stage(3, 3);

    for (int it = 0; it < NKIT; it++) {
        const int buf = it % STAGES;
        asm volatile("cp.async.wait_group 3;" ::: "memory");
        __syncthreads();
        if (it + 4 < NKIT) {
            load_stage(it + 4, (it + 4) % STAGES);
        } else {
            asm volatile("cp.async.commit_group;" ::: "memory");
        }

#pragma unroll
        for (int ks = 0; ks < 2; ks++) {
            const int kb = ks * 16;
            uint32_t a[4][4], b[4][2];
            const int mat = lane >> 3, r8 = lane & 7;
#pragma unroll
            for (int mt = 0; mt < 4; mt++) {
                int row = wm * 64 + mt * 16 + (mat & 1) * 8 + r8;
                int col = kb + (mat >> 1) * 8;
                uint32_t ad = smA + (uint32_t)(((buf * 128 + row) * SSTRIDE + col) * 2);
                asm volatile(
                    "ldmatrix.sync.aligned.m8n8.x4.shared.b16 {%0,%1,%2,%3}, [%4];"
                    : "=r"(a[mt][0]), "=r"(a[mt][1]), "=r"(a[mt][2]), "=r"(a[mt][3])
                    : "r"(ad));
            }
#pragma unroll
            for (int p = 0; p < 2; p++) {
                int nrow = wn * 32 + p * 16 + (mat >> 1) * 8 + r8;
                int col = kb + (mat & 1) * 8;
                uint32_t bd = smB + (uint32_t)(((buf * 128 + nrow) * SSTRIDE + col) * 2);
                uint32_t q0, q1, q2, q3;
                asm volatile(
                    "ldmatrix.sync.aligned.m8n8.x4.shared.b16 {%0,%1,%2,%3}, [%4];"
                    : "=r"(q0), "=r"(q1), "=r"(q2), "=r"(q3)
                    : "r"(bd));
                b[2 * p][0] = q0; b[2 * p][1] = q1;
                b[2 * p + 1][0] = q2; b[2 * p + 1][1] = q3;
            }
#pragma unroll
            for (int mt = 0; mt < 4; mt++)
#pragma unroll
                for (int nt = 0; nt < 4; nt++) {
                    asm volatile(
                        "mma.sync.aligned.m16n8k16.row.col.f32.f16.f16.f32 "
                        "{%0,%1,%2,%3}, {%4,%5,%6,%7}, {%8,%9}, {%0,%1,%2,%3};"
                        : "+f"(acc[mt][nt][0]), "+f"(acc[mt][nt][1]),
                          "+f"(acc[mt][nt][2]), "+f"(acc[mt][nt][3])
                        : "r"(a[mt][0]), "r"(a[mt][1]), "r"(a[mt][2]), "r"(a[mt][3]),
                          "r"(b[nt][0]), "r"(b[nt][1]));
                }
        }
    }

    const int rl = lane >> 2, cl = (lane & 3) * 2;
#pragma unroll
    for (int mt = 0; mt < 4; mt++) {
        int row = tm0 + wm * 64 + mt * 16 + rl;
#pragma unroll
        for (int nt = 0; nt < 4; nt++) {
            int col = tn0 + wn * 32 + nt * 8 + cl;
            *(float2*)(C + (size_t)row * 1024 + col) =
                make_float2(acc[mt][nt][0], acc[mt][nt][1]);
            *(float2*)(C + (size_t)(row + 8) * 1024 + col) =
                make_float2(acc[mt][nt][2], acc[mt][nt][3]);
        }
    }
}

// ---------------------------------------------------------------------------
// Output GEMM: out[pos][p] = P[row] . VWT[sel][p] + bo[p].
// NT=128, KTOT=KOUT=1024, rowmap scatter, per-tile B select. fp16 HMMA.
// ---------------------------------------------------------------------------
#define SM_OUT (STAGES * (128 + 128) * SSTRIDE * 2)

__global__ void __launch_bounds__(256) gemm_out_kernel(
    const __half* __restrict__ A,
    const __half* __restrict__ B0,
    const __half* __restrict__ B1,
    float* __restrict__ C,
    const float* __restrict__ bias) {
    constexpr int KTOT = KOUT;
    constexpr int NKITL = KTOT / BK;   // 32
    extern __shared__ __align__(16) char rawsm[];
    __half* AsP = (__half*)rawsm;
    __half* BsP = AsP + STAGES * 128 * SSTRIDE;

    const int tid = threadIdx.x;
    const int wid = tid >> 5, lane = tid & 31;
    const int wm = wid >> 2, wn = wid & 3;
    const int tn0 = blockIdx.x * 128;
    const int mrow0 = blockIdx.y * 128;
    const int bsel = g_tilesel[blockIdx.y];
    const __half* Bm = bsel ? B1 : B0;

    const __half* Ag = A + (size_t)mrow0 * KTOT;
    const __half* Bg = Bm + (size_t)tn0 * KTOT;

    const uint32_t smA = (uint32_t)__cvta_generic_to_shared(AsP);
    const uint32_t smB = (uint32_t)__cvta_generic_to_shared(BsP);

    float acc[4][4][4];
#pragma unroll
    for (int i = 0; i < 4; i++)
#pragma unroll
        for (int j = 0; j < 4; j++)
#pragma unroll
            for (int r = 0; r < 4; r++) acc[i][j][r] = 0.f;

    auto load_stage = [&](int it, int buf) {
        const int k0 = it * BK;
#pragma unroll
        for (int t = 0; t < 4; t++) {
            int ee = tid + t * 256;
            int row = (ee & 511) >> 2;
            int seg = ee & 3;
            const __half* gp;
            uint32_t sp;
            if (ee < 512) {
                gp = Ag + (size_t)row * KTOT + k0 + seg * 8;
                sp = smA + (uint32_t)(((buf * 128 + row) * SSTRIDE + seg * 8) * 2);
            } else {
                gp = Bg + (size_t)row * KTOT + k0 + seg * 8;
                sp = smB + (uint32_t)(((buf * 128 + row) * SSTRIDE + seg * 8) * 2);
            }
            asm volatile("cp.async.cg.shared.global [%0], [%1], 16;"
                         :: "r"(sp), "l"(gp));
        }
        asm volatile("cp.async.commit_group;" ::: "memory");
    };

    load_stage(0, 0); load_stage(1, 1); load_stage(2, 2); load_stage(3, 3);

    for (int it = 0; it < NKITL; it++) {
        const int buf = it % STAGES;
        asm volatile("cp.async.wait_group 3;" ::: "memory");
        __syncthreads();
        if (it + 4 < NKITL) {
            load_stage(it + 4, (it + 4) % STAGES);
        } else {
            asm volatile("cp.async.commit_group;" ::: "memory");
        }

#pragma unroll
        for (int ks = 0; ks < 2; ks++) {
            const int kb = ks * 16;
            uint32_t a[4][4], b[4][2];
            const int mat = lane >> 3, r8 = lane & 7;
#pragma unroll
            for (int mt = 0; mt < 4; mt++) {
                int row = wm * 64 + mt * 16 + (mat & 1) * 8 + r8;
                int col = kb + (mat >> 1) * 8;
                uint32_t ad = smA + (uint32_t)(((buf * 128 + row) * SSTRIDE + col) * 2);
                asm volatile(
                    "ldmatrix.sync.aligned.m8n8.x4.shared.b16 {%0,%1,%2,%3}, [%4];"
                    : "=r"(a[mt][0]), "=r"(a[mt][1]), "=r"(a[mt][2]), "=r"(a[mt][3])
                    : "r"(ad));
            }
#pragma unroll
            for (int p = 0; p < 2; p++) {
                int nrow = wn * 32 + p * 16 + (mat >> 1) * 8 + r8;
                int col = kb + (mat & 1) * 8;
                uint32_t bd = smB + (uint32_t)(((buf * 128 + nrow) * SSTRIDE + col) * 2);
                uint32_t q0, q1, q2, q3;
                asm volatile(
                    "ldmatrix.sync.aligned.m8n8.x4.shared.b16 {%0,%1,%2,%3}, [%4];"
                    : "=r"(q0), "=r"(q1), "=r"(q2), "=r"(q3)
                    : "r"(bd));
                b[2 * p][0] = q0; b[2 * p][1] = q1;
                b[2 * p + 1][0] = q2; b[2 * p + 1][1] = q3;
            }
#pragma unroll
            for (int mt = 0; mt < 4; mt++)
#pragma unroll
                for (int nt = 0; nt < 4; nt++) {
                    asm volatile(
                        "mma.sync.aligned.m16n8k16.row.col.f32.f16.f16.f32 "
                        "{%0,%1,%2,%3}, {%4,%5,%6,%7}, {%8,%9}, {%0,%1,%2,%3};"
                        : "+f"(acc[mt][nt][0]), "+f"(acc[mt][nt][1]),
                          "+f"(acc[mt][nt][2]), "+f"(acc[mt][nt][3])
                        : "r"(a[mt][0]), "r"(a[mt][1]), "r"(a[mt][2]), "r"(a[mt][3]),
                          "r"(b[nt][0]), "r"(b[nt][1]));
                }
        }
    }

    const int rl = lane >> 2, cl = (lane & 3) * 2;
#pragma unroll
    for (int mt = 0; mt < 4; mt++) {
        int grow = mrow0 + wm * 64 + mt * 16 + rl;
        int pos0 = g_rowmap[grow], pos1 = g_rowmap[grow + 8];
#pragma unroll
        for (int nt = 0; nt < 4; nt++) {
            int col = tn0 + wn * 32 + nt * 8 + cl;
            float b0 = bias[col], b1 = bias[col + 1];
            if (pos0 >= 0)
                *(float2*)(C + (size_t)pos0 * 1024 + col) =
                    make_float2(acc[mt][nt][0] + b0, acc[mt][nt][1] + b1);
            if (pos1 >= 0)
                *(float2*)(C + (size_t)pos1 * 1024 + col) =
                    make_float2(acc[mt][nt][2] + b0, acc[mt][nt][3] + b1);
        }
    }
}

// ---------------------------------------------------------------------------
// fp16 splits. act: [hi|lo].  weight: [hi|hi].
// ---------------------------------------------------------------------------
__device__ __forceinline__ void split_row_act(const float* __restrict__ in,
                                              __half* __restrict__ out, size_t idx) {
    int row = (int)(idx >> 10);
    int k = (int)(idx & 1023);
    float4 v = *(const float4*)(in + idx);
    __half h0 = __float2half_rn(v.x), h1 = __float2half_rn(v.y);
    __half h2 = __float2half_rn(v.z), h3 = __float2half_rn(v.w);
    __half l0 = __float2half_rn(v.x - __half2float(h0));
    __half l1 = __float2half_rn(v.y - __half2float(h1));
    __half l2 = __float2half_rn(v.z - __half2float(h2));
    __half l3 = __float2half_rn(v.w - __half2float(h3));
    __half2* o0 = (__half2*)(out + (size_t)row * GK + k);
    __half2* o1 = (__half2*)(out + (size_t)row * GK + 1024 + k);
    o0[0] = __halves2half2(h0, h1); o0[1] = __halves2half2(h2, h3);
    o1[0] = __halves2half2(l0, l1); o1[1] = __halves2half2(l2, l3);
}

__device__ __forceinline__ void split_row_w(const float* __restrict__ in,
                                            __half* __restrict__ out, size_t idx) {
    int row = (int)(idx >> 10);
    int k = (int)(idx & 1023);
    float4 v = *(const float4*)(in + idx);
    __half2 a = __halves2half2(__float2half_rn(v.x), __float2half_rn(v.y));
    __half2 b = __halves2half2(__float2half_rn(v.z), __float2half_rn(v.w));
    __half2* o0 = (__half2*)(out + (size_t)row * GK + k);
    __half2* o1 = (__half2*)(out + (size_t)row * GK + 1024 + k);
    o0[0] = a; o0[1] = b;
    o1[0] = a; o1[1] = b;
}

// blocks [0,1024)=Wq->Ws0, [1024,3072)=X->As
__global__ void __launch_bounds__(256) fused_split_kernel(
    const float* __restrict__ Wq, const float* __restrict__ X) {
    int b = blockIdx.x;
    if (b < 1024)
        split_row_w(Wq, g_Ws0, ((size_t)b * 256 + threadIdx.x) * 4);
    else
        split_row_act(X, g_As, ((size_t)(b - 1024) * 256 + threadIdx.x) * 4);
}

// ---------------------------------------------------------------------------
// c[m] = sum(keys[m]) / (sqrt(D) * ||keys[m]||)
// ---------------------------------------------------------------------------
__global__ void __launch_bounds__(256) compute_c_kernel(const float* __restrict__ keys) {
    int warp = threadIdx.x >> 5;
    int lane = threadIdx.x & 31;
    int row  = blockIdx.x * 8 + warp;
    const float4* kp = reinterpret_cast<const float4*>(keys + (size_t)row * DDIM);
    float s = 0.f, ss = 0.f;
#pragma unroll
    for (int i = 0; i < 8; i++) {
        float4 v = kp[lane + i * 32];
        s  += (v.x + v.y) + (v.z + v.w);
        ss += v.x * v.x + v.y * v.y + v.z * v.z + v.w * v.w;
    }
#pragma unroll
    for (int o = 16; o > 0; o >>= 1) {
        s  += __shfl_xor_sync(0xffffffffu, s, o);
        ss += __shfl_xor_sync(0xffffffffu, ss, o);
    }
    if (lane == 0) g_c[row] = s / (32.0f * sqrtf(ss));
}

// ---------------------------------------------------------------------------
// Fast select
// ---------------------------------------------------------------------------
__global__ void __launch_bounds__(1024) select_kernel() {
    __shared__ float wlv[32][33];
    __shared__ int   wli[32][33];
    const int tid = threadIdx.x;
    const int lane = tid & 31, w = tid >> 5;
    const int phase = blockIdx.x;

    float v[32];
#pragma unroll
    for (int j = 0; j < 32; j++) v[j] = g_c[w * 1024 + j * 32 + lane];

    float bv = v[0]; int bj = 0;
#pragma unroll
    for (int j = 1; j < 32; j++) {
        bool bet = phase ? (v[j] < bv) : (v[j] > bv);
        if (bet) { bv = v[j]; bj = j; }
    }

    for (int r = 0; r < 32; r++) {
        float cv = bv;
        int ci = w * 1024 + bj * 32 + lane;
#pragma unroll
        for (int o = 16; o > 0; o >>= 1) {
            float ov = __shfl_xor_sync(0xffffffffu, cv, o);
            int   oi = __shfl_xor_sync(0xffffffffu, ci, o);
            bool bet = phase ? ((ov < cv) || (ov == cv && oi < ci))
                             : ((ov > cv) || (ov == cv && oi < ci));
            if (bet) { cv = ov; ci = oi; }
        }
        if (lane == 0) { wlv[w][r] = cv; wli[w][r] = ci; }
        int wlane = ci & 31;
        if (lane == wlane && r < 31) {
            int wj = (ci >> 5) & 31;
            v[wj] = phase ? INFINITY : -INFINITY;
            bv = v[0]; bj = 0;
#pragma unroll
            for (int j = 1; j < 32; j++) {
                bool bet = phase ? (v[j] < bv) : (v[j] > bv);
                if (bet) { bv = v[j]; bj = j; }
            }
        }
    }
    __syncthreads();

    if (w == 0) {
        int ptr = 0;
        for (int r = 0; r < 32; r++) {
            float hv = wlv[lane][ptr];
            int   hidx = wli[lane][ptr];
            float cv = hv; int ci = hidx;
#pragma unroll
            for (int o = 16; o > 0; o >>= 1) {
                float ov = __shfl_xor_sync(0xffffffffu, cv, o);
                int   oi = __shfl_xor_sync(0xffffffffu, ci, o);
                bool bet = phase ? ((ov < cv) || (ov == cv && oi < ci))
                                 : ((ov > cv) || (ov == cv && oi < ci));
                if (bet) { cv = ov; ci = oi; }
            }
            if (hv == cv && hidx == ci) ptr++;
            if (lane == 0) g_sel[phase][r] = ci;
        }
    }
}

// ---------------------------------------------------------------------------
// wbar + sign(qm)
// ---------------------------------------------------------------------------
__global__ void __launch_bounds__(128) wbar_kernel(const float* __restrict__ Wq) {
    int col = blockIdx.x * 128 + threadIdx.x;
    int o0 = blockIdx.y * 32;
    float s = 0.f;
#pragma unroll 8
    for (int o = 0; o < 32; o++)
        s += Wq[(size_t)(o0 + o) * DDIM + col];
    g_wpart[blockIdx.y][col] = s;
}

__global__ void __launch_bounds__(256) qm_sign_kernel(const float* __restrict__ X) {
    __shared__ float wb[DDIM];
    const int tid = threadIdx.x;
    for (int c = tid; c < DDIM; c += 256) {
        float s = 0.f;
#pragma unroll
        for (int by = 0; by < 32; by++) s += g_wpart[by][c];
        wb[c] = s;
    }
    __syncthreads();
    const int lane = tid & 31, w = tid >> 5;
    int row = blockIdx.x * 8 + w;
    const float4* xp = reinterpret_cast<const float4*>(X + (size_t)row * DDIM);
    const float4* wp = reinterpret_cast<const float4*>(wb);
    float s = 0.f;
#pragma unroll
    for (int i = 0; i < 8; i++) {
        float4 a = xp[lane + i * 32];
        float4 b = wp[lane + i * 32];
        s += a.x * b.x + a.y * b.y + a.z * b.z + a.w * b.w;
    }
#pragma unroll
    for (int o = 16; o > 0; o >>= 1) s += __shfl_xor_sync(0xffffffffu, s, o);
    if (lane == 0) g_sign[row] = (s >= 0.f) ? 0 : 1;
}

// ---------------------------------------------------------------------------
// Stable partition
// ---------------------------------------------------------------------------
__global__ void __launch_bounds__(1024) perm_kernel() {
    __shared__ int sa[2048];
    __shared__ int sb[2048];
    const int tid = threadIdx.x;
    int z0 = (g_sign[tid] == 0);
    int z1 = (g_sign[tid + 1024] == 0);
    sa[tid] = z0; sa[tid + 1024] = z1;
    __syncthreads();
    int* src = sa; int* dst = sb;
    for (int off = 1; off < 2048; off <<= 1) {
        int i0 = tid, i1 = tid + 1024;
        dst[i0] = src[i0] + (i0 >= off ? src[i0 - off] : 0);
        dst[i1] = src[i1] + (i1 >= off ? src[i1 - off] : 0);
        __syncthreads();
        int* t = src; src = dst; dst = t;
    }
    int* scan = src;
    int M0 = scan[2047];
    int t0 = (M0 + 127) >> 7;
    int G1 = t0 << 7;

    g_rowmap[tid] = -1;
    g_rowmap[tid + 1024] = -1;
    if (tid < MPAD - 2048) g_rowmap[2048 + tid] = -1;
    __syncthreads();

    int d0 = z0 ? (scan[tid] - 1) : (G1 + tid - scan[tid]);
    int i1 = tid + 1024;
    int d1 = z1 ? (scan[i1] - 1) : (G1 + i1 - scan[i1]);
    g_permdst[tid] = d0;
    g_permdst[i1] = d1;
    g_rowmap[d0] = tid;
    g_rowmap[d1] = i1;
    if (tid < NTILES) g_tilesel[tid] = (tid < t0) ? 0 : 1;
}

// ---------------------------------------------------------------------------
// K/V projections
// ---------------------------------------------------------------------------
__global__ void __launch_bounds__(256) kvproj_kernel(const float* __restrict__ keys,
                                                     const float* __restrict__ vals,
                                                     const float* __restrict__ Wk,
                                                     const float* __restrict__ Wv) {
    __shared__ float As[32][64];
    __shared__ float Bs[64][68];
    __shared__ int sidx[32];
    const int tid = threadIdx.x;
    const int col0 = blockIdx.x * 64;
    const int sel = blockIdx.y;
    const int mat = blockIdx.z;
    const float* src = mat ? vals : keys;
    const float* W   = mat ? Wv : Wk;
    float* dst = mat ? &g_vproj[sel][0][0] : &g_kproj[sel][0][0];
    if (tid < 32) sidx[tid] = g_sel[sel][tid];
    __syncthreads();
    const int tx = tid & 7, ty = tid >> 3;
    float acc[8] = {};
    for (int kk = 0; kk < DDIM; kk += 64) {
#pragma unroll
        for (int t = 0; t < 2; t++) {
            int e = tid + t * 256;
            int slot = e >> 4, f4 = e & 15;
            *reinterpret_cast<float4*>(&As[slot][f4 * 4]) =
                *reinterpret_cast<const float4*>(&src[(size_t)sidx[slot] * DDIM + kk + f4 * 4]);
        }
#pragma unroll
        for (int t = 0; t < 4; t++) {
            int e = tid + t * 256;
            int col = e >> 4, f4 = e & 15;
            float4 v = *reinterpret_cast<const float4*>(&W[(size_t)(col0 + col) * DDIM + kk + f4 * 4]);
            Bs[f4 * 4 + 0][col] = v.x; Bs[f4 * 4 + 1][col] = v.y;
            Bs[f4 * 4 + 2][col] = v.z; Bs[f4 * 4 + 3][col] = v.w;
        }
        __syncthreads();
#pragma unroll
        for (int k = 0; k < 64; k++) {
            float a = As[ty][k];
#pragma unroll
            for (int j = 0; j < 8; j++)
                acc[j] = fmaf(a, Bs[k][tx * 8 + j], acc[j]);
        }
        __syncthreads();
    }
#pragma unroll
    for (int j = 0; j < 8; j += 4)
        *reinterpret_cast<float4*>(&dst[(size_t)ty * DDIM + col0 + tx * 8 + j]) =
            make_float4(acc[j], acc[j + 1], acc[j + 2], acc[j + 3]);
}

// ---------------------------------------------------------------------------
// VWT[sel][p][h*32+slot] = sum_e Vproj[sel][slot][h*64+e] * Wo[p][h*64+e]
// fp16 [hi|hi] epilogue over K=1024.
// ---------------------------------------------------------------------------
__global__ void __launch_bounds__(256) vw_kernel(const float* __restrict__ Wo) {
    __shared__ float Vp[32][68];
    __shared__ float Wos[64][68];
    const int tid = threadIdx.x;
    const int pt = blockIdx.x, h = blockIdx.y, sel = blockIdx.z;
#pragma unroll
    for (int t = 0; t < 2; t++) {
        int e = tid + t * 256;
        int slot = e >> 4, f4 = e & 15;
        *(float4*)(&Vp[slot][f4 * 4]) =
            *(const float4*)(&g_vproj[sel][slot][h * 64 + f4 * 4]);
    }
#pragma unroll
    for (int t = 0; t < 4; t++) {
        int e = tid + t * 256;
        int pl = e >> 4, f4 = e & 15;
        *(float4*)(&Wos[pl][f4 * 4]) =
            *(const float4*)(&Wo[(size_t)(pt * 64 + pl) * DDIM + h * 64 + f4 * 4]);
    }
    __syncthreads();
    const int pl = tid >> 2, s0 = (tid & 3) * 8;
    float acc[8] = {};
#pragma unroll
    for (int k4 = 0; k4 < 16; k4++) {
        float4 w = *(const float4*)(&Wos[pl][k4 * 4]);
#pragma unroll
        for (int j = 0; j < 8; j++) {
            float4 vv = *(const float4*)(&Vp[s0 + j][k4 * 4]);
            acc[j] = fmaf(w.x, vv.x, acc[j]);
            acc[j] = fmaf(w.y, vv.y, acc[j]);
            acc[j] = fmaf(w.z, vv.z, acc[j]);
            acc[j] = fmaf(w.w, vv.w, acc[j]);
        }
    }
    const int p = pt * 64 + pl;
    __half* out = &g_VWTs[sel][p][0];
#pragma unroll
    for (int j = 0; j < 8; j++) {
        int hs = h * 32 + s0 + j;
        __half hi = __float2half_rn(acc[j]);
        out[hs] = hi; out[512 + hs] = hi;
    }
}

// ---------------------------------------------------------------------------
// scores+softmax: 32 pos x 16 heads -> g_p[pos][h*32+slot]
// ---------------------------------------------------------------------------
__global__ void __launch_bounds__(256) scores_kernel() {
    __shared__ float Ks[2][32][65];
    __shared__ float qs[32][65];
    __shared__ int ssel[32];
    const int tid = threadIdx.x;
    const int p0 = blockIdx.x * 32;
    const int h = blockIdx.y;

#pragma unroll
    for (int t = 0; t < 4; t++) {
        int e = tid + t * 256;
        int sel = e >> 9, slot = (e >> 4) & 31, f4 = e & 15;
        float4 v = *(const float4*)(&g_kproj[sel][slot][h * 64 + f4 * 4]);
        Ks[sel][slot][f4 * 4 + 0] = v.x; Ks[sel][slot][f4 * 4 + 1] = v.y;
        Ks[sel][slot][f4 * 4 + 2] = v.z; Ks[sel][slot][f4 * 4 + 3] = v.w;
    }
#pragma unroll
    for (int t = 0; t < 2; t++) {
        int e = tid + t * 256;
        int pos = e >> 4, f4 = e & 15;
        float4 v = *(const float4*)(&g_q[(size_t)(p0 + pos) * DDIM + h * 64 + f4 * 4]);
        qs[pos][f4 * 4 + 0] = v.x; qs[pos][f4 * 4 + 1] = v.y;
        qs[pos][f4 * 4 + 2] = v.z; qs[pos][f4 * 4 + 3] = v.w;
    }
    if (tid < 32) ssel[tid] = g_sign[p0 + tid];
    __syncthreads();

    const int w = tid >> 5, lane = tid & 31;
#pragma unroll
    for (int pi = 0; pi < 4; pi++) {
        int pos = w * 4 + pi;
        int sel = ssel[pos];
        const float* kr = &Ks[sel][lane][0];
        const float* qr = &qs[pos][0];
        float s = 0.f;
#pragma unroll
        for (int k = 0; k < 64; k++) s = fmaf(qr[k], kr[k], s);
        s *= 0.125f;
        float mx = s;
#pragma unroll
        for (int o = 16; o > 0; o >>= 1)
            mx = fmaxf(mx, __shfl_xor_sync(0xffffffffu, mx, o));
        float e = expf(s - mx);
        float sm = e;
#pragma unroll
        for (int o = 16; o > 0; o >>= 1)
            sm += __shfl_xor_sync(0xffffffffu, sm, o);
        g_p[(size_t)(p0 + pos) * 512 + h * 32 + lane] = e / sm;
    }
}

// ---------------------------------------------------------------------------
// pack P: g_Ps[permdst[pos]] = fp16 split(g_p[pos]) [hi|lo] over K=1024
// ---------------------------------------------------------------------------
__global__ void __launch_bounds__(128) packp_kernel() {
    const int pos = blockIdx.x;
    const int dst = g_permdst[pos];
    const int k = threadIdx.x * 4;
    float4 v = *(const float4*)(g_p + (size_t)pos * 512 + k);
    __half h0 = __float2half_rn(v.x), h1 = __float2half_rn(v.y);
    __half h2 = __float2half_rn(v.z), h3 = __float2half_rn(v.w);
    __half l0 = __float2half_rn(v.x - __half2float(h0));
    __half l1 = __float2half_rn(v.y - __half2float(h1));
    __half l2 = __float2half_rn(v.z - __half2float(h2));
    __half l3 = __float2half_rn(v.w - __half2float(h3));
    size_t base = (size_t)dst * KOUT + k;
    *(__half2*)(g_Ps + base)       = __halves2half2(h0, h1);
    *(__half2*)(g_Ps + base + 2)   = __halves2half2(h2, h3);
    *(__half2*)(g_Ps + base + 512) = __halves2half2(l0, l1);
    *(__half2*)(g_Ps + base + 514) = __halves2half2(l2, l3);
}

// ---------------------------------------------------------------------------
// avg_attn + sel_idx
// ---------------------------------------------------------------------------
__global__ void __launch_bounds__(256) avgsel_kernel(float* __restrict__ out_attn,
                                                     float* __restrict__ out_selidx) {
    const int tid = threadIdx.x;
    const int pos = blockIdx.x * 8 + (tid >> 5);
    const int slot = tid & 31;
    float s = 0.f;
#pragma unroll
    for (int hh = 0; hh < NHEAD; hh++)
        s += g_p[(size_t)pos * 512 + hh * 32 + slot];
    if (out_attn)
        out_attn[(size_t)pos * KSEL + slot] = s * (1.f / NHEAD);
    if (out_selidx)
        out_selidx[(size_t)pos * KSEL + slot] = (float)g_sel[g_sign[pos]][slot];
}

// ---------------------------------------------------------------------------
// LayerNorm in-place
// ---------------------------------------------------------------------------
__global__ void __launch_bounds__(256) ln_kernel(float* __restrict__ io,
                                                 const float* __restrict__ gamma,
                                                 const float* __restrict__ beta) {
    int row = blockIdx.x;
    float4* p = reinterpret_cast<float4*>(io + (size_t)row * DDIM);
    float4 v = p[threadIdx.x];
    float s  = (v.x + v.y) + (v.z + v.w);
    float ss = v.x * v.x + v.y * v.y + v.z * v.z + v.w * v.w;
    __shared__ float r1[8], r2[8];
    __shared__ float fmu, frs;
    int lane = threadIdx.x & 31, w = threadIdx.x >> 5;
#pragma unroll
    for (int o = 16; o > 0; o >>= 1) {
        s  += __shfl_xor_sync(0xffffffffu, s, o);
        ss += __shfl_xor_sync(0xffffffffu, ss, o);
    }
    if (lane == 0) { r1[w] = s; r2[w] = ss; }
    __syncthreads();
    if (threadIdx.x == 0) {
        float ts = 0.f, tss = 0.f;
#pragma unroll
        for (int i = 0; i < 8; i++) { ts += r1[i]; tss += r2[i]; }
        float mu  = ts * (1.f / 1024.f);
        float var = tss * (1.f / 1024.f) - mu * mu;
        fmu = mu;
        frs = rsqrtf(var + 1e-5f);
    }
    __syncthreads();
    float mu = fmu, rstd = frs;
    const float4 g = reinterpret_cast<const float4*>(gamma)[threadIdx.x];
    const float4 b = reinterpret_cast<const float4*>(beta)[threadIdx.x];
    v.x = (v.x - mu) * rstd * g.x + b.x;
    v.y = (v.y - mu) * rstd * g.y + b.y;
    v.z = (v.z - mu) * rstd * g.z + b.z;
    v.w = (v.w - mu) * rstd * g.w + b.w;
    p[threadIdx.x] = v;
}

// ---------------------------------------------------------------------------
extern "C" void kernel_launch(void* const* d_in, const int* in_sizes, int n_in,
                              void* d_out, int out_size) {
    const float* X     = (const float*)d_in[0];
    const float* keys  = (const float*)d_in[1];
    const float* vals  = (const float*)d_in[2];
    const float* Wq    = (const float*)d_in[3];
    const float* Wk    = (const float*)d_in[4];
    const float* Wv    = (const float*)d_in[5];
    const float* Wo    = (const float*)d_in[6];
    const float* bo    = (const float*)d_in[7];
    const float* gamma = (const float*)d_in[8];
    const float* beta  = (const float*)d_in[9];

    float* out = (float*)d_out;
    float* out_attn = nullptr;
    float* out_sel  = nullptr;
    const long long base = (long long)BN_POS * DDIM;
    if ((long long)out_size >= base + (long long)BN_POS * KSEL)
        out_attn = out + base;
    if ((long long)out_size >= base + 2LL * BN_POS * KSEL)
        out_sel = out + base + (long long)BN_POS * KSEL;

    void *pAs = nullptr, *pWs0 = nullptr, *pQ = nullptr, *pPs = nullptr, *pVW = nullptr;
    cudaGetSymbolAddress(&pAs, g_As);
    cudaGetSymbolAddress(&pWs0, g_Ws0);
    cudaGetSymbolAddress(&pQ, g_q);
    cudaGetSymbolAddress(&pPs, g_Ps);
    cudaGetSymbolAddress(&pVW, g_VWTs);
    __half* VW0 = (__half*)pVW;
    __half* VW1 = VW0 + (size_t)1024 * KOUT;

    cudaFuncSetAttribute(gemm_mma_kernel,
                         cudaFuncAttributeMaxDynamicSharedMemorySize, GEMM_SMEM);
    cudaFuncSetAttribute(gemm_out_kernel,
                         cudaFuncAttributeMaxDynamicSharedMemorySize, SM_OUT);

    static cudaStream_t s2 = nullptr, s3 = nullptr;
    static cudaEvent_t evFork = nullptr, ev2 = nullptr, ev2b = nullptr, ev3 = nullptr;
    if (!s2) {
        cudaStreamCreateWithFlags(&s2, cudaStreamNonBlocking);
        cudaStreamCreateWithFlags(&s3, cudaStreamNonBlocking);
        cudaEventCreateWithFlags(&evFork, cudaEventDisableTiming);
        cudaEventCreateWithFlags(&ev2, cudaEventDisableTiming);
        cudaEventCreateWithFlags(&ev2b, cudaEventDisableTiming);
        cudaEventCreateWithFlags(&ev3, cudaEventDisableTiming);
    }

    cudaEventRecord(evFork, 0);
    cudaStreamWaitEvent(s2, evFork, 0);
    cudaStreamWaitEvent(s3, evFork, 0);

    // ---- s2: selection chain; ev2 gates scores, ev2b gates gemm_out ----
    compute_c_kernel<<<MDIM / 8, 256, 0, s2>>>(keys);
    select_kernel<<<2, 1024, 0, s2>>>();
    kvproj_kernel<<<dim3(16, 2, 2), 256, 0, s2>>>(keys, vals, Wk, Wv);
    cudaEventRecord(ev2, s2);                 // scores needs only kproj
    vw_kernel<<<dim3(16, 16, 2), 256, 0, s2>>>(Wo);
    cudaEventRecord(ev2b, s2);                // gemm_out needs VWT

    // ---- s3: sign + permutation ----
    wbar_kernel<<<dim3(8, 32), 128, 0, s3>>>(Wq);
    qm_sign_kernel<<<BN_POS / 8, 256, 0, s3>>>(X);
    perm_kernel<<<1, 1024, 0, s3>>>();
    cudaEventRecord(ev3, s3);

    // ---- main: split + q-proj GEMM (independent of selection) ----
    fused_split_kernel<<<3072, 256>>>(Wq, X);
    gemm_mma_kernel<<<dim3(8, 16), 256, GEMM_SMEM>>>(
        (const __half*)pAs, (const __half*)pWs0, (float*)pQ);

    cudaStreamWaitEvent(0, ev2, 0);
    cudaStreamWaitEvent(0, ev3, 0);

    // ---- attention + output ----
    scores_kernel<<<dim3(BN_POS / 32, NHEAD), 256>>>();
    packp_kernel<<<BN_POS, 128>>>();
    avgsel_kernel<<<BN_POS / 8, 256>>>(out_attn, out_sel);
    cudaStreamWaitEvent(0, ev2b, 0);
    gemm_out_kernel<<<dim3(8, NTILES), 256, SM_OUT>>>(
        (const __half*)pPs, VW0, VW1, out, bo);
    ln_kernel<<<BN_POS, 256>>>(out, gamma, beta);
}